// round 1
// baseline (speedup 1.0000x reference)
#include <cuda_runtime.h>

// Scratch accumulators (no device allocation allowed).
__device__ double g_S[32];
__device__ double g_sq;

__global__ void init_kernel() {
    int t = threadIdx.x;
    if (t < 32) g_S[t] = 0.0;
    if (t == 32) g_sq = 0.0;
}

__global__ void __launch_bounds__(256, 8) reduce_kernel(
    const float* __restrict__ data,
    const float* __restrict__ pred,
    long long total4)  // number of float4 elements = N*D/4
{
    const int tid = threadIdx.x;
    const int colgrp = tid & 7;                 // which float4 within a 32-col row
    const float4 p4 = reinterpret_cast<const float4*>(pred)[colgrp];

    const float4* __restrict__ d4 = reinterpret_cast<const float4*>(data);

    float s0 = 0.f, s1 = 0.f, s2 = 0.f, s3 = 0.f;
    float sq = 0.f;

    long long idx = (long long)blockIdx.x * blockDim.x + tid;
    const long long stride = (long long)gridDim.x * blockDim.x;  // multiple of 8

    for (; idx < total4; idx += stride) {
        float4 v = d4[idx];
        float d0 = v.x - p4.x;
        float d1 = v.y - p4.y;
        float d2 = v.z - p4.z;
        float d3 = v.w - p4.w;
        s0 += d0; s1 += d1; s2 += d2; s3 += d3;
        sq = fmaf(d0, d0, sq);
        sq = fmaf(d1, d1, sq);
        sq = fmaf(d2, d2, sq);
        sq = fmaf(d3, d3, sq);
    }

    // Warp reduce: lanes {l, l+8, l+16, l+24} share the same columns.
    unsigned full = 0xFFFFFFFFu;
    s0 += __shfl_xor_sync(full, s0, 8);
    s1 += __shfl_xor_sync(full, s1, 8);
    s2 += __shfl_xor_sync(full, s2, 8);
    s3 += __shfl_xor_sync(full, s3, 8);
    s0 += __shfl_xor_sync(full, s0, 16);
    s1 += __shfl_xor_sync(full, s1, 16);
    s2 += __shfl_xor_sync(full, s2, 16);
    s3 += __shfl_xor_sync(full, s3, 16);
    // Full warp reduce for sumsq.
    sq += __shfl_xor_sync(full, sq, 16);
    sq += __shfl_xor_sync(full, sq, 8);
    sq += __shfl_xor_sync(full, sq, 4);
    sq += __shfl_xor_sync(full, sq, 2);
    sq += __shfl_xor_sync(full, sq, 1);

    __shared__ float sS[8][8][4];   // [warp][colgrp][component]
    __shared__ float sSq[8];
    const int warp = tid >> 5;
    const int lane = tid & 31;
    if (lane < 8) {
        sS[warp][lane][0] = s0;
        sS[warp][lane][1] = s1;
        sS[warp][lane][2] = s2;
        sS[warp][lane][3] = s3;
    }
    if (lane == 0) sSq[warp] = sq;
    __syncthreads();

    // Threads 0..31 each own one of the 32 columns: col = g*4 + k.
    if (tid < 32) {
        const int g = tid >> 2;      // colgrp 0..7
        const int k = tid & 3;       // component 0..3
        float acc = 0.f;
        #pragma unroll
        for (int w = 0; w < 8; w++) acc += sS[w][g][k];
        atomicAdd(&g_S[g * 4 + k], (double)acc);
    }
    if (tid == 32) {
        float acc = 0.f;
        #pragma unroll
        for (int w = 0; w < 8; w++) acc += sSq[w];
        atomicAdd(&g_sq, (double)acc);
    }
}

__global__ void finalize_kernel(float* __restrict__ out) {
    int lane = threadIdx.x;
    double s = g_S[lane];
    double v = s * s;
    unsigned full = 0xFFFFFFFFu;
    v += __shfl_xor_sync(full, v, 16);
    v += __shfl_xor_sync(full, v, 8);
    v += __shfl_xor_sync(full, v, 4);
    v += __shfl_xor_sync(full, v, 2);
    v += __shfl_xor_sync(full, v, 1);
    if (lane == 0) {
        out[0] = (float)((v - g_sq) / 32.0);
    }
}

extern "C" void kernel_launch(void* const* d_in, const int* in_sizes, int n_in,
                              void* d_out, int out_size) {
    const float* data = (const float*)d_in[0];   // output: [N, 32] fp32
    const float* pred = (const float*)d_in[1];   // pred_avg: [32] fp32
    long long total4 = (long long)in_sizes[0] / 4;

    init_kernel<<<1, 64>>>();
    // 148 SMs * 8 blocks -> full occupancy wave coverage, grid-stride handles rest.
    reduce_kernel<<<1184, 256>>>(data, pred, total4);
    finalize_kernel<<<1, 32>>>((float*)d_out);
}